// round 1
// baseline (speedup 1.0000x reference)
#include <cuda_runtime.h>
#include <cstdint>

#define BB 8
#define CC 512
#define NNODES 2048
#define TT 24

// ---------------- scratch (static device arrays; no allocation) ----------------
__device__ float g_f1 [BB*TT*NNODES];   // f1[b][t][n]
__device__ float g_f1c[BB*TT*NNODES];   // dilated conv of f1
__device__ float g_f2 [BB*CC*TT];       // f2[b][c][t]  (atomically accumulated)
__device__ float g_f2c[BB*CC*TT];       // dilated conv of f2
__device__ float g_g  [BB*TT*CC];       // g[b][t][c] = f1c @ w
__device__ float g_l  [BB*TT*TT];       // l[b][i][k]
__device__ float g_stats[2*TT];         // per-k sum, sumsq (atomically accumulated)

// ---------------- packed f32x2 helpers ----------------
__device__ __forceinline__ unsigned long long fma2(unsigned long long a, unsigned long long b, unsigned long long c){
    unsigned long long d;
    asm("fma.rn.f32x2 %0, %1, %2, %3;" : "=l"(d) : "l"(a), "l"(b), "l"(c));
    return d;
}
__device__ __forceinline__ unsigned long long add2(unsigned long long a, unsigned long long b){
    unsigned long long d;
    asm("add.rn.f32x2 %0, %1, %2;" : "=l"(d) : "l"(a), "l"(b));
    return d;
}
__device__ __forceinline__ unsigned long long pack2(float f){
    unsigned long long r;
    asm("mov.b64 %0, {%1, %1};" : "=l"(r) : "f"(f));
    return r;
}
__device__ __forceinline__ float2 unpk2(unsigned long long v){
    float2 f;
    asm("mov.b64 {%0, %1}, %2;" : "=f"(f.x), "=f"(f.y) : "l"(v));
    return f;
}

// ---------------- K0: zero accumulated scratch ----------------
__global__ void k0_zero(){
    int idx = blockIdx.x * 256 + threadIdx.x;
    if (idx < BB*CC*TT) g_f2[idx] = 0.0f;
    if (idx < 2*TT)     g_stats[idx] = 0.0f;
}

// ---------------- K1: fused dual weighted reduction over seq ----------------
// grid = 8*64 blocks, block = 192 threads (6 warps).
// warp w handles t-quad [4w, 4w+4); lane = c-lane; thread covers c = lane + 32*cc, cc<16.
// Block covers n-tile of 32 and the FULL c range (so f1 stores are exact).
__global__ void __launch_bounds__(192, 2)
k1_reduce(const float* __restrict__ seq, const float* __restrict__ w1, const float* __restrict__ w2){
    const int b    = blockIdx.x >> 6;
    const int n0   = (blockIdx.x & 63) * 32;
    const int warp = threadIdx.x >> 5;   // t-quad
    const int lane = threadIdx.x & 31;   // c-lane

    unsigned long long w1p[16];
#pragma unroll
    for (int cc = 0; cc < 16; ++cc) w1p[cc] = pack2(w1[cc*32 + lane]);

    unsigned long long acc2[16][2];
#pragma unroll
    for (int cc = 0; cc < 16; ++cc){ acc2[cc][0] = 0ull; acc2[cc][1] = 0ull; }

    const char* base = (const char*)seq +
        ((((size_t)b*CC + lane)*NNODES + n0)*TT + warp*4) * sizeof(float);
    const size_t cc_stride = (size_t)32 * NNODES * TT * sizeof(float); // 6291456 B

    for (int nn = 0; nn < 32; ++nn){
        const int n = n0 + nn;
        const unsigned long long w2p = pack2(w2[n]);
        unsigned long long p0 = 0ull, p1 = 0ull;
#pragma unroll
        for (int cc = 0; cc < 16; ++cc){
            ulonglong2 x = *reinterpret_cast<const ulonglong2*>(base + cc*cc_stride + (size_t)nn*96);
            p0 = fma2(w1p[cc], x.x, p0);
            p1 = fma2(w1p[cc], x.y, p1);
            acc2[cc][0] = fma2(w2p, x.x, acc2[cc][0]);
            acc2[cc][1] = fma2(w2p, x.y, acc2[cc][1]);
        }
        // butterfly reduce over the 32 c-lanes
#pragma unroll
        for (int off = 16; off > 0; off >>= 1){
            p0 = add2(p0, __shfl_xor_sync(0xffffffffu, p0, off));
            p1 = add2(p1, __shfl_xor_sync(0xffffffffu, p1, off));
        }
        if (lane == 0){
            float2 a = unpk2(p0), c = unpk2(p1);
            float* o = g_f1 + ((size_t)b*TT + warp*4)*NNODES + n;
            o[0]        = a.x;
            o[NNODES]   = a.y;
            o[2*NNODES] = c.x;
            o[3*NNODES] = c.y;
        }
    }
    // flush f2 partials
#pragma unroll
    for (int cc = 0; cc < 16; ++cc){
        const int c = cc*32 + lane;
        float* o = g_f2 + ((size_t)b*CC + c)*TT + warp*4;
        float2 a = unpk2(acc2[cc][0]), d = unpk2(acc2[cc][1]);
        atomicAdd(o + 0, a.x);
        atomicAdd(o + 1, a.y);
        atomicAdd(o + 2, d.x);
        atomicAdd(o + 3, d.y);
    }
}

// ---------------- K2a: dilated conv of f1 over the n axis ----------------
// f1c[b,t,n] = sum_i f1[b,i,n-1]*Wd1[t,i,0] + f1[b,i,n+1]*Wd1[t,i,1]
// grid = 8*16, block = 256 (n-chunks of 128)
__global__ void k2a_conv1(const float* __restrict__ Wd1){
    const int b  = blockIdx.x >> 4;
    const int n0 = (blockIdx.x & 15) * 128;
    __shared__ float s1[TT][130];       // col j <-> n = n0 + j - 1
    __shared__ float sw[TT][48];        // Wd1[t][i][k] -> sw[t][2i+k]
    for (int idx = threadIdx.x; idx < TT*48; idx += 256)
        ((float*)sw)[idx] = Wd1[idx];
    for (int idx = threadIdx.x; idx < TT*130; idx += 256){
        int i = idx / 130, j = idx % 130;
        int n = n0 + j - 1;
        s1[i][j] = (n >= 0 && n < NNODES) ? g_f1[((size_t)b*TT + i)*NNODES + n] : 0.0f;
    }
    __syncthreads();
#pragma unroll
    for (int u = 0; u < 12; ++u){
        int idx = threadIdx.x + u*256;   // 3072 outputs
        int t = idx >> 7, nl = idx & 127;
        float acc = 0.0f;
#pragma unroll
        for (int i = 0; i < TT; ++i)
            acc += s1[i][nl] * sw[t][2*i] + s1[i][nl+2] * sw[t][2*i+1];
        g_f1c[((size_t)b*TT + t)*NNODES + n0 + nl] = acc;
    }
}

// ---------------- K2b: dilated conv of f2 over the t axis ----------------
// f2c[b,o,t] = sum_i Wd2[o,i,0]*f2[b,i,t-1] + Wd2[o,i,1]*f2[b,i,t+1]
// grid = 8*16 (o-chunks of 32), block = 128 (32 o-lanes x 4 t-groups of 6)
__global__ void k2b_conv2(const float* __restrict__ Wd2){
    const int b  = blockIdx.x >> 4;
    const int o  = (blockIdx.x & 15) * 32 + (threadIdx.x & 31);
    const int tg = threadIdx.x >> 5;    // 0..3, t = 6*tg + u
    __shared__ float sf[256][26];       // col j <-> t = j - 1 (zero halo at 0, 25)
    float acc[6] = {0,0,0,0,0,0};
    for (int half = 0; half < 2; ++half){
        for (int idx = threadIdx.x; idx < 256*26; idx += 128){
            int i = idx / 26, j = idx % 26;
            sf[i][j] = (j >= 1 && j <= TT) ? g_f2[((size_t)b*CC + half*256 + i)*TT + (j-1)] : 0.0f;
        }
        __syncthreads();
#pragma unroll 4
        for (int i = 0; i < 256; ++i){
            float2 wv = *reinterpret_cast<const float2*>(&Wd2[((size_t)o*CC + half*256 + i)*2]);
#pragma unroll
            for (int u = 0; u < 6; ++u){
                int t = tg*6 + u;
                acc[u] += wv.x * sf[i][t] + wv.y * sf[i][t+2];
            }
        }
        __syncthreads();
    }
#pragma unroll
    for (int u = 0; u < 6; ++u)
        g_f2c[((size_t)b*CC + o)*TT + tg*6 + u] = acc[u];
}

// ---------------- K2c: g[b,t,c] = sum_n f1c[b,t,n] * w[n,c] ----------------
// grid = 8*16 (c-chunks of 32), block = 96: tq=tid/8 handles t=tq and t=tq+12, cq=tid%8 -> 4 c's
__global__ void __launch_bounds__(96) k2c_gemm(const float* __restrict__ w){
    const int b  = blockIdx.x >> 4;
    const int c0 = (blockIdx.x & 15) * 32;
    const int tid = threadIdx.x;
    const int tq = tid >> 3;            // 0..11
    const int cq = tid & 7;
    __shared__ __align__(16) float sA[TT*129];
    __shared__ __align__(16) float sB[128*36];
    unsigned long long acc[4] = {0ull,0ull,0ull,0ull};
    for (int kt = 0; kt < 16; ++kt){
        const int n0 = kt << 7;
        for (int idx = tid; idx < 3072; idx += 96){
            int r = idx >> 7, col = idx & 127;
            sA[r*129 + col] = g_f1c[((size_t)b*TT + r)*NNODES + n0 + col];
        }
        for (int idx = tid; idx < 4096; idx += 96){
            int r = idx >> 5, cl = idx & 31;
            sB[r*36 + cl] = w[(size_t)(n0 + r)*CC + c0 + cl];
        }
        __syncthreads();
#pragma unroll 4
        for (int r = 0; r < 128; ++r){
            unsigned long long a0 = pack2(sA[tq*129 + r]);
            unsigned long long a1 = pack2(sA[(tq+12)*129 + r]);
            ulonglong2 bv = *reinterpret_cast<const ulonglong2*>(&sB[r*36 + cq*4]);
            acc[0] = fma2(a0, bv.x, acc[0]);
            acc[1] = fma2(a0, bv.y, acc[1]);
            acc[2] = fma2(a1, bv.x, acc[2]);
            acc[3] = fma2(a1, bv.y, acc[3]);
        }
        __syncthreads();
    }
    float2 r0 = unpk2(acc[0]), r1 = unpk2(acc[1]), r2 = unpk2(acc[2]), r3 = unpk2(acc[3]);
    float* o0 = g_g + ((size_t)b*TT + tq)*CC + c0 + cq*4;
    o0[0] = r0.x; o0[1] = r0.y; o0[2] = r1.x; o0[3] = r1.y;
    float* o1 = g_g + ((size_t)b*TT + tq + 12)*CC + c0 + cq*4;
    o1[0] = r2.x; o1[1] = r2.y; o1[2] = r3.x; o1[3] = r3.y;
}

// ---------------- K2d1: s = sigmoid(g @ f2c + b); l = v @ s; BN stats ----------------
// grid = 8 (per batch), block = 192
__global__ void k2d1_attn(const float* __restrict__ bbias, const float* __restrict__ v){
    const int b = blockIdx.x;
    __shared__ float ss[TT][25];
#pragma unroll
    for (int u = 0; u < 3; ++u){
        int idx = threadIdx.x + u*192;   // 576 outputs
        int j = idx / TT, k = idx % TT;
        float acc = bbias[j*TT + k];
        const float* gp = g_g   + ((size_t)b*TT + j)*CC;
        const float* fp = g_f2c + (size_t)b*CC*TT + k;
#pragma unroll 8
        for (int c = 0; c < CC; ++c) acc += gp[c] * fp[(size_t)c*TT];
        ss[j][k] = 1.0f / (1.0f + __expf(-acc));
    }
    __syncthreads();
#pragma unroll
    for (int u = 0; u < 3; ++u){
        int idx = threadIdx.x + u*192;
        int i = idx / TT, k = idx % TT;
        float acc = 0.0f;
#pragma unroll
        for (int j = 0; j < TT; ++j) acc += v[i*TT + j] * ss[j][k];
        g_l[((size_t)b*TT + i)*TT + k] = acc;
        atomicAdd(&g_stats[k], acc);
        atomicAdd(&g_stats[TT + k], acc*acc);
    }
}

// ---------------- K2d2: BN + mask + softmax ----------------
// 1 block, 192 threads = one (b,i) row each
__global__ void k2d2_final(const float* __restrict__ gamma, const float* __restrict__ beta,
                           float* __restrict__ out){
    const int tid = threadIdx.x;
    __shared__ float smean[TT], sinv[TT];
    if (tid < TT){
        float mean = g_stats[tid] * (1.0f/192.0f);
        float var  = g_stats[TT + tid] * (1.0f/192.0f) - mean*mean;
        smean[tid] = mean;
        sinv[tid]  = rsqrtf(var + 1e-5f);
    }
    __syncthreads();
    const int b = tid / TT, i = tid % TT;
    float vals[TT];
    float mx = -3.4e38f;
#pragma unroll
    for (int k = 0; k < TT; ++k){
        float y = (g_l[((size_t)b*TT + i)*TT + k] - smean[k]) * sinv[k] * gamma[k] + beta[k];
        if ((i < 12) != (k < 12)) y -= 1e13f;
        vals[k] = y;
        mx = fmaxf(mx, y);
    }
    float s = 0.0f;
#pragma unroll
    for (int k = 0; k < TT; ++k){ float e = __expf(vals[k] - mx); vals[k] = e; s += e; }
    float inv = 1.0f / s;
#pragma unroll
    for (int k = 0; k < TT; ++k)
        out[((size_t)b*TT + i)*TT + k] = vals[k] * inv;
}

// ---------------- launch ----------------
extern "C" void kernel_launch(void* const* d_in, const int* in_sizes, int n_in,
                              void* d_out, int out_size){
    const float* seq   = (const float*)d_in[0];
    const float* w1    = (const float*)d_in[1];
    const float* w2    = (const float*)d_in[2];
    const float* Wd1   = (const float*)d_in[3];
    const float* Wd2   = (const float*)d_in[4];
    const float* w     = (const float*)d_in[5];
    const float* bbias = (const float*)d_in[6];
    const float* v     = (const float*)d_in[7];
    const float* gamma = (const float*)d_in[8];
    const float* beta  = (const float*)d_in[9];
    float* out = (float*)d_out;

    k0_zero   <<<(BB*CC*TT + 255)/256, 256>>>();
    k1_reduce <<<BB*64, 192>>>(seq, w1, w2);
    k2a_conv1 <<<BB*16, 256>>>(Wd1);
    k2b_conv2 <<<BB*16, 128>>>(Wd2);
    k2c_gemm  <<<BB*16, 96>>>(w);
    k2d1_attn <<<BB, 192>>>(bbias, v);
    k2d2_final<<<1, 192>>>(gamma, beta, out);
}

// round 3
// speedup vs baseline: 1.3546x; 1.3546x over previous
#include <cuda_runtime.h>
#include <cstdint>

#define BB 8
#define CC 512
#define NNODES 2048
#define TT 24

typedef unsigned long long ull;

// ---------------- scratch (static device arrays; no allocation) ----------------
__device__ float g_f1  [BB*TT*NNODES];   // f1[b][t][n]
__device__ float g_f1c [BB*TT*NNODES];   // dilated conv of f1
__device__ float g_f2  [BB*CC*TT];       // f2[b][c][t]  (atomically accumulated)
__device__ float g_f2cT[BB*TT*CC];       // dilated conv of f2, TRANSPOSED: [b][t][c]
__device__ float g_g   [BB*TT*CC];       // g[b][t][c] = f1c @ w
__device__ float g_s   [BB*TT*TT];       // sigmoid attention matrix

// ---------------- packed f32x2 helpers ----------------
__device__ __forceinline__ ull fma2(ull a, ull b, ull c){
    ull d;
    asm("fma.rn.f32x2 %0, %1, %2, %3;" : "=l"(d) : "l"(a), "l"(b), "l"(c));
    return d;
}
__device__ __forceinline__ ull add2(ull a, ull b){
    ull d;
    asm("add.rn.f32x2 %0, %1, %2;" : "=l"(d) : "l"(a), "l"(b));
    return d;
}
__device__ __forceinline__ ull pack2(float f){
    ull r;
    asm("mov.b64 %0, {%1, %1};" : "=l"(r) : "f"(f));
    return r;
}
__device__ __forceinline__ float2 unpk2(ull v){
    float2 f;
    asm("mov.b64 {%0, %1}, %2;" : "=f"(f.x), "=f"(f.y) : "l"(v));
    return f;
}

// ---------------- K0: zero accumulated scratch ----------------
__global__ void k0_zero(){
    int idx = blockIdx.x * 256 + threadIdx.x;
    if (idx < BB*CC*TT) g_f2[idx] = 0.0f;
}

// ---------------- K1: fused dual weighted reduction over seq ----------------
// grid = 8*32 blocks (n-chunks of 64), block = 192 threads (6 warps).
// warp w handles t-quad [4w, 4w+4); lane = c-lane; thread covers c = lane + 32*cc, cc<16.
__global__ void __launch_bounds__(192, 2)
k1_reduce(const float* __restrict__ seq, const float* __restrict__ w1, const float* __restrict__ w2){
    const int b    = blockIdx.x >> 5;
    const int n0   = (blockIdx.x & 31) * 64;
    const int warp = threadIdx.x >> 5;   // t-quad
    const int lane = threadIdx.x & 31;   // c-lane

    ull w1p[16];
#pragma unroll
    for (int cc = 0; cc < 16; ++cc) w1p[cc] = pack2(w1[cc*32 + lane]);

    ull acc2[16][2];
#pragma unroll
    for (int cc = 0; cc < 16; ++cc){ acc2[cc][0] = 0ull; acc2[cc][1] = 0ull; }

    const char* base = (const char*)seq +
        ((((size_t)b*CC + lane)*NNODES + n0)*TT + warp*4) * sizeof(float);
    const size_t cc_stride = (size_t)32 * NNODES * TT * sizeof(float);

    for (int nn = 0; nn < 64; ++nn){
        const int n = n0 + nn;
        const ull w2p = pack2(w2[n]);
        ull p0 = 0ull, p1 = 0ull;
#pragma unroll
        for (int cc = 0; cc < 16; ++cc){
            ulonglong2 x = *reinterpret_cast<const ulonglong2*>(base + cc*cc_stride + (size_t)nn*96);
            p0 = fma2(w1p[cc], x.x, p0);
            p1 = fma2(w1p[cc], x.y, p1);
            acc2[cc][0] = fma2(w2p, x.x, acc2[cc][0]);
            acc2[cc][1] = fma2(w2p, x.y, acc2[cc][1]);
        }
#pragma unroll
        for (int off = 16; off > 0; off >>= 1){
            p0 = add2(p0, __shfl_xor_sync(0xffffffffu, p0, off));
            p1 = add2(p1, __shfl_xor_sync(0xffffffffu, p1, off));
        }
        if (lane == 0){
            float2 a = unpk2(p0), c = unpk2(p1);
            float* o = g_f1 + ((size_t)b*TT + warp*4)*NNODES + n;
            o[0]        = a.x;
            o[NNODES]   = a.y;
            o[2*NNODES] = c.x;
            o[3*NNODES] = c.y;
        }
    }
#pragma unroll
    for (int cc = 0; cc < 16; ++cc){
        const int c = cc*32 + lane;
        float* o = g_f2 + ((size_t)b*CC + c)*TT + warp*4;
        float2 a = unpk2(acc2[cc][0]), d = unpk2(acc2[cc][1]);
        atomicAdd(o + 0, a.x);
        atomicAdd(o + 1, a.y);
        atomicAdd(o + 2, d.x);
        atomicAdd(o + 3, d.y);
    }
}

// ---------------- K2a: dilated conv of f1 over the n axis ----------------
__global__ void k2a_conv1(const float* __restrict__ Wd1){
    const int b  = blockIdx.x >> 4;
    const int n0 = (blockIdx.x & 15) * 128;
    __shared__ float s1[TT][130];
    __shared__ float sw[TT][48];
    for (int idx = threadIdx.x; idx < TT*48; idx += 256)
        ((float*)sw)[idx] = Wd1[idx];
    for (int idx = threadIdx.x; idx < TT*130; idx += 256){
        int i = idx / 130, j = idx % 130;
        int n = n0 + j - 1;
        s1[i][j] = (n >= 0 && n < NNODES) ? g_f1[((size_t)b*TT + i)*NNODES + n] : 0.0f;
    }
    __syncthreads();
#pragma unroll
    for (int u = 0; u < 12; ++u){
        int idx = threadIdx.x + u*256;
        int t = idx >> 7, nl = idx & 127;
        float acc = 0.0f;
#pragma unroll
        for (int i = 0; i < TT; ++i)
            acc += s1[i][nl] * sw[t][2*i] + s1[i][nl+2] * sw[t][2*i+1];
        g_f1c[((size_t)b*TT + t)*NNODES + n0 + nl] = acc;
    }
}

// ---------------- K2b: dilated conv of f2 over the t axis (REWRITTEN) ----------------
// f2cT[b,t,o] = sum_i Wd2[o,i,0]*f2[b,i,t-1] + Wd2[o,i,1]*f2[b,i,t+1]
// grid = 8 b * 16 o-chunks(32), block = 128 (32 o-lanes x 4 t-groups of 6).
// Wd2 staged in smem coalesced; f2 staged per i-chunk; packed fma2 over t-pairs.
__global__ void __launch_bounds__(128) k2b_conv2(const float* __restrict__ Wd2){
    const int b     = blockIdx.x >> 4;
    const int o0    = (blockIdx.x & 15) * 32;
    const int olane = threadIdx.x & 31;
    const int tg    = threadIdx.x >> 5;   // 0..3
    const int t0    = tg * 6;             // even

    __shared__ float  sf[64][26];         // sf[i][j]: j<->t=j-1; cols 0,25 are zero halo
    __shared__ float2 sw2[32][65];        // padded: conflict-free 64-bit LDS across o-lanes

    if (threadIdx.x < 64){ sf[threadIdx.x][0] = 0.f; sf[threadIdx.x][25] = 0.f; }

    ull acc01 = 0ull, acc23 = 0ull, acc45 = 0ull;
    const float2* wsrc = reinterpret_cast<const float2*>(Wd2);

    for (int ic = 0; ic < 8; ++ic){
        __syncthreads();
        // stage f2 chunk: rows contiguous in global (t fastest)
#pragma unroll
        for (int u = 0; u < 12; ++u){
            int idx = threadIdx.x + u*128;      // 0..1535
            int i = idx / 24, t = idx % 24;
            sf[i][t+1] = g_f2[((size_t)b*CC + ic*64 + i)*TT + t];
        }
        // stage Wd2 chunk coalesced: [32 o][64 i] float2
#pragma unroll
        for (int u = 0; u < 16; ++u){
            int idx = threadIdx.x + u*128;      // 0..2047
            int oo = idx >> 6, iz = idx & 63;
            sw2[oo][iz] = wsrc[(size_t)(o0+oo)*512 + ic*64 + iz];
        }
        __syncthreads();
#pragma unroll 8
        for (int iz = 0; iz < 64; ++iz){
            float2 wv = sw2[olane][iz];
            ull wx = pack2(wv.x), wy = pack2(wv.y);
            const ull* row = reinterpret_cast<const ull*>(&sf[iz][0]);
            ull P0 = row[t0/2], P1 = row[t0/2+1], P2 = row[t0/2+2], P3 = row[t0/2+3];
            acc01 = fma2(wx, P0, acc01); acc01 = fma2(wy, P1, acc01);
            acc23 = fma2(wx, P1, acc23); acc23 = fma2(wy, P2, acc23);
            acc45 = fma2(wx, P2, acc45); acc45 = fma2(wy, P3, acc45);
        }
    }
    float2 r01 = unpk2(acc01), r23 = unpk2(acc23), r45 = unpk2(acc45);
    float* ob = g_f2cT + (size_t)b*TT*CC + o0 + olane;
    ob[(t0+0)*CC] = r01.x;
    ob[(t0+1)*CC] = r01.y;
    ob[(t0+2)*CC] = r23.x;
    ob[(t0+3)*CC] = r23.y;
    ob[(t0+4)*CC] = r45.x;
    ob[(t0+5)*CC] = r45.y;
}

// ---------------- K2c: g[b,t,c] = sum_n f1c[b,t,n] * w[n,c] ----------------
// grid = 8*16 (c-chunks of 32), block = 192: tq=tid/8 -> one t, cq=tid%8 -> 4 c
__global__ void __launch_bounds__(192) k2c_gemm(const float* __restrict__ w){
    const int b  = blockIdx.x >> 4;
    const int c0 = (blockIdx.x & 15) * 32;
    const int tid = threadIdx.x;
    const int tq = tid >> 3;            // 0..23
    const int cq = tid & 7;
    __shared__ __align__(16) float sA[TT*129];
    __shared__ __align__(16) float sB[128*36];
    ull acc[2] = {0ull,0ull};
    for (int kt = 0; kt < 16; ++kt){
        const int n0 = kt << 7;
        for (int idx = tid; idx < 3072; idx += 192){
            int r = idx >> 7, col = idx & 127;
            sA[r*129 + col] = g_f1c[((size_t)b*TT + r)*NNODES + n0 + col];
        }
        for (int idx = tid; idx < 4096; idx += 192){
            int r = idx >> 5, cl = idx & 31;
            sB[r*36 + cl] = w[(size_t)(n0 + r)*CC + c0 + cl];
        }
        __syncthreads();
#pragma unroll 8
        for (int r = 0; r < 128; ++r){
            ull a0 = pack2(sA[tq*129 + r]);
            ulonglong2 bv = *reinterpret_cast<const ulonglong2*>(&sB[r*36 + cq*4]);
            acc[0] = fma2(a0, bv.x, acc[0]);
            acc[1] = fma2(a0, bv.y, acc[1]);
        }
        __syncthreads();
    }
    float2 r0 = unpk2(acc[0]), r1 = unpk2(acc[1]);
    float* o0 = g_g + ((size_t)b*TT + tq)*CC + c0 + cq*4;
    o0[0] = r0.x; o0[1] = r0.y; o0[2] = r1.x; o0[3] = r1.y;
}

// ---------------- K2d1: s = sigmoid(g @ f2cT^T + bias) (REWRITTEN) ----------------
// grid = 8, block = 192. Both operands c-contiguous; staged in smem, packed fma2.
// Thread: j = tid/8, computes k = (tid%8)*3 + {0,1,2} -> g row cached across 3 outputs.
__global__ void __launch_bounds__(192) k2d1_attn(const float* __restrict__ bbias){
    const int b = blockIdx.x;
    const int tid = threadIdx.x;
    const int j = tid >> 3;
    const int kbase = (tid & 7) * 3;
    __shared__ float sg [24][130];   // pitch 130: 8B-aligned rows, stride==2 mod 32
    __shared__ float sfT[24][130];
    ull acc0 = 0ull, acc1 = 0ull, acc2v = 0ull;
    for (int ch = 0; ch < 4; ++ch){
        __syncthreads();
        for (int idx = tid; idx < 24*128; idx += 192){
            int r = idx >> 7, c = idx & 127;
            sg[r][c]  = g_g   [((size_t)b*TT + r)*CC + ch*128 + c];
            sfT[r][c] = g_f2cT[((size_t)b*TT + r)*CC + ch*128 + c];
        }
        __syncthreads();
        const ull* gr  = reinterpret_cast<const ull*>(&sg[j][0]);
        const ull* fr0 = reinterpret_cast<const ull*>(&sfT[kbase+0][0]);
        const ull* fr1 = reinterpret_cast<const ull*>(&sfT[kbase+1][0]);
        const ull* fr2 = reinterpret_cast<const ull*>(&sfT[kbase+2][0]);
#pragma unroll 16
        for (int cp = 0; cp < 64; ++cp){
            ull gv = gr[cp];
            acc0  = fma2(gv, fr0[cp], acc0);
            acc1  = fma2(gv, fr1[cp], acc1);
            acc2v = fma2(gv, fr2[cp], acc2v);
        }
    }
    float2 a0 = unpk2(acc0), a1 = unpk2(acc1), a2 = unpk2(acc2v);
    float s0 = a0.x + a0.y + bbias[j*TT + kbase+0];
    float s1 = a1.x + a1.y + bbias[j*TT + kbase+1];
    float s2 = a2.x + a2.y + bbias[j*TT + kbase+2];
    float* os = g_s + ((size_t)b*TT + j)*TT + kbase;
    os[0] = 1.0f/(1.0f + __expf(-s0));
    os[1] = 1.0f/(1.0f + __expf(-s1));
    os[2] = 1.0f/(1.0f + __expf(-s2));
}

// ---------------- K2d2: l = v @ s; BN (in-block stats) + mask + softmax ----------------
// single block, 192 threads = one (b,i) row each; everything in smem, no atomics
__global__ void k2d2_final(const float* __restrict__ v, const float* __restrict__ gamma,
                           const float* __restrict__ beta, float* __restrict__ out){
    const int tid = threadIdx.x;
    __shared__ float ss[BB][TT][TT];     // 18 KB
    __shared__ float sv[TT][TT];
    __shared__ float sl[192][25];        // pitch 25 -> conflict-free column sums
    __shared__ float smean[TT], sinv[TT];
    for (int idx = tid; idx < BB*TT*TT; idx += 192) ((float*)ss)[idx] = g_s[idx];
    for (int idx = tid; idx < TT*TT;   idx += 192) ((float*)sv)[idx] = v[idx];
    __syncthreads();
    const int b = tid / TT, i = tid % TT;
    float l[TT];
#pragma unroll
    for (int k = 0; k < TT; ++k) l[k] = 0.0f;
#pragma unroll
    for (int jj = 0; jj < TT; ++jj){
        float vij = sv[i][jj];
#pragma unroll
        for (int k = 0; k < TT; ++k) l[k] = fmaf(vij, ss[b][jj][k], l[k]);
    }
#pragma unroll
    for (int k = 0; k < TT; ++k) sl[tid][k] = l[k];
    __syncthreads();
    if (tid < TT){
        float s = 0.0f, s2 = 0.0f;
        for (int r = 0; r < 192; ++r){ float x = sl[r][tid]; s += x; s2 = fmaf(x, x, s2); }
        float m = s * (1.0f/192.0f);
        smean[tid] = m;
        sinv[tid]  = rsqrtf(s2 * (1.0f/192.0f) - m*m + 1e-5f);
    }
    __syncthreads();
    float mx = -3.4e38f;
#pragma unroll
    for (int k = 0; k < TT; ++k){
        float y = (l[k] - smean[k]) * sinv[k] * gamma[k] + beta[k];
        if ((i < 12) != (k < 12)) y -= 1e13f;
        l[k] = y;
        mx = fmaxf(mx, y);
    }
    float s = 0.0f;
#pragma unroll
    for (int k = 0; k < TT; ++k){ float e = __expf(l[k] - mx); l[k] = e; s += e; }
    float inv = 1.0f / s;
#pragma unroll
    for (int k = 0; k < TT; ++k)
        out[((size_t)b*TT + i)*TT + k] = l[k] * inv;
}

// ---------------- launch ----------------
extern "C" void kernel_launch(void* const* d_in, const int* in_sizes, int n_in,
                              void* d_out, int out_size){
    const float* seq   = (const float*)d_in[0];
    const float* w1    = (const float*)d_in[1];
    const float* w2    = (const float*)d_in[2];
    const float* Wd1   = (const float*)d_in[3];
    const float* Wd2   = (const float*)d_in[4];
    const float* w     = (const float*)d_in[5];
    const float* bbias = (const float*)d_in[6];
    const float* v     = (const float*)d_in[7];
    const float* gamma = (const float*)d_in[8];
    const float* beta  = (const float*)d_in[9];
    float* out = (float*)d_out;

    k0_zero   <<<(BB*CC*TT + 255)/256, 256>>>();
    k1_reduce <<<BB*32, 192>>>(seq, w1, w2);
    k2a_conv1 <<<BB*16, 256>>>(Wd1);
    k2b_conv2 <<<BB*16, 128>>>(Wd2);
    k2c_gemm  <<<BB*16, 192>>>(w);
    k2d1_attn <<<BB, 192>>>(bbias);
    k2d2_final<<<1, 192>>>(v, gamma, beta, out);
}

// round 4
// speedup vs baseline: 1.7600x; 1.2993x over previous
#include <cuda_runtime.h>
#include <cstdint>

#define BB 8
#define CC 512
#define NNODES 2048
#define TT 24

typedef unsigned long long ull;

// ---------------- scratch (static device arrays; no allocation) ----------------
__device__ float g_f1  [BB*TT*NNODES];   // f1[b][t][n]
__device__ float g_f1c [BB*TT*NNODES];   // dilated conv of f1
__device__ float g_f2  [BB*CC*TT];       // f2[b][c][t]     (atomically accumulated)
__device__ float g_f2cT[BB*TT*CC];       // f2c transposed: [b][t][c]  (atomically accumulated)
__device__ float g_g   [BB*TT*CC];       // g[b][t][c] = f1c @ w       (atomically accumulated)
__device__ float g_s   [BB*TT*TT];       // sigmoid attention matrix

// ---------------- packed f32x2 helpers ----------------
__device__ __forceinline__ ull fma2(ull a, ull b, ull c){
    ull d;
    asm("fma.rn.f32x2 %0, %1, %2, %3;" : "=l"(d) : "l"(a), "l"(b), "l"(c));
    return d;
}
__device__ __forceinline__ ull add2(ull a, ull b){
    ull d;
    asm("add.rn.f32x2 %0, %1, %2;" : "=l"(d) : "l"(a), "l"(b));
    return d;
}
__device__ __forceinline__ ull pack2(float f){
    ull r;
    asm("mov.b64 %0, {%1, %1};" : "=l"(r) : "f"(f));
    return r;
}
__device__ __forceinline__ float2 unpk2(ull v){
    float2 f;
    asm("mov.b64 {%0, %1}, %2;" : "=f"(f.x), "=f"(f.y) : "l"(v));
    return f;
}

// ---------------- K0: zero accumulated scratch ----------------
__global__ void k0_zero(){
    int idx = blockIdx.x * 256 + threadIdx.x;
    if (idx < BB*CC*TT){
        g_f2  [idx] = 0.0f;
        g_f2cT[idx] = 0.0f;
        g_g   [idx] = 0.0f;
    }
}

// ---------------- K1: fused dual weighted reduction over seq ----------------
// grid = 8*32 blocks (n-chunks of 64), block = 192 threads (6 warps).
// warp w handles t-quad [4w, 4w+4); lane = c-lane; thread covers c = lane + 32*cc, cc<16.
__global__ void __launch_bounds__(192, 2)
k1_reduce(const float* __restrict__ seq, const float* __restrict__ w1, const float* __restrict__ w2){
    const int b    = blockIdx.x >> 5;
    const int n0   = (blockIdx.x & 31) * 64;
    const int warp = threadIdx.x >> 5;   // t-quad
    const int lane = threadIdx.x & 31;   // c-lane

    ull w1p[16];
#pragma unroll
    for (int cc = 0; cc < 16; ++cc) w1p[cc] = pack2(w1[cc*32 + lane]);

    ull acc2[16][2];
#pragma unroll
    for (int cc = 0; cc < 16; ++cc){ acc2[cc][0] = 0ull; acc2[cc][1] = 0ull; }

    const char* base = (const char*)seq +
        ((((size_t)b*CC + lane)*NNODES + n0)*TT + warp*4) * sizeof(float);
    const size_t cc_stride = (size_t)32 * NNODES * TT * sizeof(float);

    for (int nn = 0; nn < 64; ++nn){
        const int n = n0 + nn;
        const ull w2p = pack2(w2[n]);
        ull p0 = 0ull, p1 = 0ull;
#pragma unroll
        for (int cc = 0; cc < 16; ++cc){
            ulonglong2 x = *reinterpret_cast<const ulonglong2*>(base + cc*cc_stride + (size_t)nn*96);
            p0 = fma2(w1p[cc], x.x, p0);
            p1 = fma2(w1p[cc], x.y, p1);
            acc2[cc][0] = fma2(w2p, x.x, acc2[cc][0]);
            acc2[cc][1] = fma2(w2p, x.y, acc2[cc][1]);
        }
#pragma unroll
        for (int off = 16; off > 0; off >>= 1){
            p0 = add2(p0, __shfl_xor_sync(0xffffffffu, p0, off));
            p1 = add2(p1, __shfl_xor_sync(0xffffffffu, p1, off));
        }
        if (lane == 0){
            float2 a = unpk2(p0), c = unpk2(p1);
            float* o = g_f1 + ((size_t)b*TT + warp*4)*NNODES + n;
            o[0]        = a.x;
            o[NNODES]   = a.y;
            o[2*NNODES] = c.x;
            o[3*NNODES] = c.y;
        }
    }
#pragma unroll
    for (int cc = 0; cc < 16; ++cc){
        const int c = cc*32 + lane;
        float* o = g_f2 + ((size_t)b*CC + c)*TT + warp*4;
        float2 a = unpk2(acc2[cc][0]), d = unpk2(acc2[cc][1]);
        atomicAdd(o + 0, a.x);
        atomicAdd(o + 1, a.y);
        atomicAdd(o + 2, d.x);
        atomicAdd(o + 3, d.y);
    }
}

// ---------------- K2a: dilated conv of f1 over the n axis ----------------
__global__ void k2a_conv1(const float* __restrict__ Wd1){
    const int b  = blockIdx.x >> 4;
    const int n0 = (blockIdx.x & 15) * 128;
    __shared__ float s1[TT][130];
    __shared__ float sw[TT][48];
    for (int idx = threadIdx.x; idx < TT*48; idx += 256)
        ((float*)sw)[idx] = Wd1[idx];
    for (int idx = threadIdx.x; idx < TT*130; idx += 256){
        int i = idx / 130, j = idx % 130;
        int n = n0 + j - 1;
        s1[i][j] = (n >= 0 && n < NNODES) ? g_f1[((size_t)b*TT + i)*NNODES + n] : 0.0f;
    }
    __syncthreads();
#pragma unroll
    for (int u = 0; u < 12; ++u){
        int idx = threadIdx.x + u*256;
        int t = idx >> 7, nl = idx & 127;
        float acc = 0.0f;
#pragma unroll
        for (int i = 0; i < TT; ++i)
            acc += s1[i][nl] * sw[t][2*i] + s1[i][nl+2] * sw[t][2*i+1];
        g_f1c[((size_t)b*TT + t)*NNODES + n0 + nl] = acc;
    }
}

// ---------------- K2b: dilated conv of f2 over the t axis (K-SPLIT GEMM) ----------------
// f2cT[b,t,o] += sum_{i in chunk} Wd2[o,i,0]*f2[b,i,t-1] + Wd2[o,i,1]*f2[b,i,t+1]
// grid = 16 o-chunks(32) x 16 i-chunks(32) = 256 blocks, block = 256 (32 o-lanes x 8 b).
// Single staging round, register accumulation for all 24 t, RED-add at the end.
__global__ void __launch_bounds__(256) k2b_conv2(const float* __restrict__ Wd2){
    const int o0 = (blockIdx.x & 15) * 32;
    const int i0 = (blockIdx.x >> 4) * 32;
    const int tid   = threadIdx.x;
    const int olane = tid & 31;
    const int b     = tid >> 5;

    __shared__ __align__(16) float  sf[32][8][26];  // [i][b][j], j = t+1, halo at 0/25
    __shared__ float2 sw2[32][33];                  // [o][i] padded

    // halo zeros (exactly 256 (i,b) pairs)
    {
        int i = tid >> 3, bb = tid & 7;
        sf[i][bb][0] = 0.0f; sf[i][bb][25] = 0.0f;
    }
    // stage f2 chunk: 32 i x 8 b x 24 t
#pragma unroll
    for (int u = 0; u < 24; ++u){
        int idx = tid + u*256;
        int i = idx / 192, r = idx % 192;
        int bb = r / 24, t = r % 24;
        sf[i][bb][t+1] = g_f2[((size_t)bb*CC + i0 + i)*TT + t];
    }
    // stage Wd2 tile: 32 o x 32 i float2
    const float2* wsrc = reinterpret_cast<const float2*>(Wd2);
#pragma unroll
    for (int u = 0; u < 4; ++u){
        int idx = tid + u*256;
        int oo = idx >> 5, iz = idx & 31;
        sw2[oo][iz] = wsrc[(size_t)(o0+oo)*CC + i0 + iz];
    }
    __syncthreads();

    ull acc[12];
#pragma unroll
    for (int u = 0; u < 12; ++u) acc[u] = 0ull;
#pragma unroll 4
    for (int iz = 0; iz < 32; ++iz){
        float2 wv = sw2[olane][iz];
        ull wx = pack2(wv.x), wy = pack2(wv.y);
        const ull* R = reinterpret_cast<const ull*>(&sf[iz][b][0]);  // 13 ull, warp-broadcast
#pragma unroll
        for (int u = 0; u < 12; ++u){
            acc[u] = fma2(wx, R[u], acc[u]);
            acc[u] = fma2(wy, R[u+1], acc[u]);
        }
    }
    float* ob = g_f2cT + (size_t)b*TT*CC + o0 + olane;
#pragma unroll
    for (int u = 0; u < 12; ++u){
        float2 r = unpk2(acc[u]);
        atomicAdd(&ob[(2*u  )*CC], r.x);
        atomicAdd(&ob[(2*u+1)*CC], r.y);
    }
}

// ---------------- K2c: g[b,t,c] += sum_n f1c[b,t,n] * w[n,c]  (K-SPLIT x4) ----------------
// grid = 8b x 16 c-chunks(32) x 4 k-splits = 512 blocks, block = 192
__global__ void __launch_bounds__(192) k2c_gemm(const float* __restrict__ w){
    const int b  = blockIdx.x >> 6;
    const int c0 = ((blockIdx.x >> 2) & 15) * 32;
    const int ks = blockIdx.x & 3;
    const int tid = threadIdx.x;
    const int tq = tid >> 3;            // 0..23 -> t
    const int cq = tid & 7;             // 4 c's
    __shared__ __align__(16) float sA[TT*129];
    __shared__ __align__(16) float sB[128*36];
    ull acc[2] = {0ull, 0ull};
    for (int kt = 0; kt < 4; ++kt){
        const int n0 = ks*512 + kt*128;
        for (int idx = tid; idx < 3072; idx += 192){
            int r = idx >> 7, col = idx & 127;
            sA[r*129 + col] = g_f1c[((size_t)b*TT + r)*NNODES + n0 + col];
        }
        for (int idx = tid; idx < 4096; idx += 192){
            int r = idx >> 5, cl = idx & 31;
            sB[r*36 + cl] = w[(size_t)(n0 + r)*CC + c0 + cl];
        }
        __syncthreads();
#pragma unroll 8
        for (int r = 0; r < 128; ++r){
            ull a0 = pack2(sA[tq*129 + r]);
            ulonglong2 bv = *reinterpret_cast<const ulonglong2*>(&sB[r*36 + cq*4]);
            acc[0] = fma2(a0, bv.x, acc[0]);
            acc[1] = fma2(a0, bv.y, acc[1]);
        }
        __syncthreads();
    }
    float2 r0 = unpk2(acc[0]), r1 = unpk2(acc[1]);
    float* o0 = g_g + ((size_t)b*TT + tq)*CC + c0 + cq*4;
    atomicAdd(&o0[0], r0.x);
    atomicAdd(&o0[1], r0.y);
    atomicAdd(&o0[2], r1.x);
    atomicAdd(&o0[3], r1.y);
}

// ---------------- K2d1: s[b,j,k] = sigmoid(g[b,j,:] . f2cT[b,k,:] + bias) ----------------
// grid = 8b x 24j = 192 blocks, block = 128 (4 warps x 6 k each)
__global__ void __launch_bounds__(128) k2d1_attn(const float* __restrict__ bbias){
    const int b = blockIdx.x / 24;
    const int j = blockIdx.x % 24;
    const int tid  = threadIdx.x;
    const int wrp  = tid >> 5;
    const int lane = tid & 31;
    __shared__ __align__(16) float sg[CC];
    const float* grow = g_g + ((size_t)b*TT + j)*CC;
#pragma unroll
    for (int u = 0; u < 4; ++u) sg[tid + u*128] = grow[tid + u*128];
    __syncthreads();
    const ull* sg2 = reinterpret_cast<const ull*>(sg);
    const ull* f0  = reinterpret_cast<const ull*>(g_f2cT + ((size_t)b*TT + wrp*6)*CC);
    ull acc[6] = {0ull,0ull,0ull,0ull,0ull,0ull};
#pragma unroll
    for (int it = 0; it < 8; ++it){
        ull gv = sg2[lane + it*32];
#pragma unroll
        for (int kk = 0; kk < 6; ++kk)
            acc[kk] = fma2(f0[(size_t)kk*256 + lane + it*32], gv, acc[kk]);
    }
#pragma unroll
    for (int kk = 0; kk < 6; ++kk)
#pragma unroll
        for (int off = 16; off > 0; off >>= 1)
            acc[kk] = add2(acc[kk], __shfl_xor_sync(0xffffffffu, acc[kk], off));
    if (lane < 6){
        int k = wrp*6 + lane;
        float2 aa = unpk2(acc[lane]);
        float sv = aa.x + aa.y + bbias[j*TT + k];
        g_s[((size_t)b*TT + j)*TT + k] = 1.0f/(1.0f + __expf(-sv));
    }
}

// ---------------- K2d2: l = v @ s; BN (in-block stats) + mask + softmax ----------------
// single block, 192 threads = one (b,i) row each; everything in smem, no atomics
__global__ void k2d2_final(const float* __restrict__ v, const float* __restrict__ gamma,
                           const float* __restrict__ beta, float* __restrict__ out){
    const int tid = threadIdx.x;
    __shared__ float ss[BB][TT][TT];
    __shared__ float sv[TT][TT];
    __shared__ float sl[192][25];
    __shared__ float smean[TT], sinv[TT];
    for (int idx = tid; idx < BB*TT*TT; idx += 192) ((float*)ss)[idx] = g_s[idx];
    for (int idx = tid; idx < TT*TT;   idx += 192) ((float*)sv)[idx] = v[idx];
    __syncthreads();
    const int b = tid / TT, i = tid % TT;
    float l[TT];
#pragma unroll
    for (int k = 0; k < TT; ++k) l[k] = 0.0f;
#pragma unroll
    for (int jj = 0; jj < TT; ++jj){
        float vij = sv[i][jj];
#pragma unroll
        for (int k = 0; k < TT; ++k) l[k] = fmaf(vij, ss[b][jj][k], l[k]);
    }
#pragma unroll
    for (int k = 0; k < TT; ++k) sl[tid][k] = l[k];
    __syncthreads();
    if (tid < TT){
        float s = 0.0f, s2 = 0.0f;
        for (int r = 0; r < 192; ++r){ float x = sl[r][tid]; s += x; s2 = fmaf(x, x, s2); }
        float m = s * (1.0f/192.0f);
        smean[tid] = m;
        sinv[tid]  = rsqrtf(s2 * (1.0f/192.0f) - m*m + 1e-5f);
    }
    __syncthreads();
    float mx = -3.4e38f;
#pragma unroll
    for (int k = 0; k < TT; ++k){
        float y = (l[k] - smean[k]) * sinv[k] * gamma[k] + beta[k];
        if ((i < 12) != (k < 12)) y -= 1e13f;
        l[k] = y;
        mx = fmaxf(mx, y);
    }
    float s = 0.0f;
#pragma unroll
    for (int k = 0; k < TT; ++k){ float e = __expf(l[k] - mx); l[k] = e; s += e; }
    float inv = 1.0f / s;
#pragma unroll
    for (int k = 0; k < TT; ++k)
        out[((size_t)b*TT + i)*TT + k] = l[k] * inv;
}

// ---------------- launch ----------------
extern "C" void kernel_launch(void* const* d_in, const int* in_sizes, int n_in,
                              void* d_out, int out_size){
    const float* seq   = (const float*)d_in[0];
    const float* w1    = (const float*)d_in[1];
    const float* w2    = (const float*)d_in[2];
    const float* Wd1   = (const float*)d_in[3];
    const float* Wd2   = (const float*)d_in[4];
    const float* w     = (const float*)d_in[5];
    const float* bbias = (const float*)d_in[6];
    const float* v     = (const float*)d_in[7];
    const float* gamma = (const float*)d_in[8];
    const float* beta  = (const float*)d_in[9];
    float* out = (float*)d_out;

    k0_zero   <<<(BB*CC*TT + 255)/256, 256>>>();
    k1_reduce <<<BB*32, 192>>>(seq, w1, w2);
    k2a_conv1 <<<BB*16, 256>>>(Wd1);
    k2b_conv2 <<<256, 256>>>(Wd2);
    k2c_gemm  <<<512, 192>>>(w);
    k2d1_attn <<<BB*TT, 128>>>(bbias);
    k2d2_final<<<1, 192>>>(v, gamma, beta, out);
}